// round 1
// baseline (speedup 1.0000x reference)
#include <cuda_runtime.h>

#define NP 100000
#define ND 50000
#define EMAX 600000

// ~188 MB of scratch, bump-allocated below. Static __device__ array per harness rules.
static const size_t TOTAL_BYTES = 200ull * 1024 * 1024;
__device__ __align__(256) unsigned char g_mem[TOTAL_BYTES];

// ---------------------------------------------------------------------------
// Setup kernels: degree count, inv-sqrt, exclusive scan, CSR fill
// ---------------------------------------------------------------------------

__global__ void count_kernel(const int* __restrict__ idx, int* __restrict__ cnt, int E) {
    int e = blockIdx.x * blockDim.x + threadIdx.x;
    if (e < E) atomicAdd(&cnt[idx[e]], 1);
}

__global__ void inv_kernel(const int* __restrict__ cnt, float* __restrict__ inv, int n) {
    int i = blockIdx.x * blockDim.x + threadIdx.x;
    if (i < n) {
        int c = cnt[i];
        if (c < 1) c = 1;
        inv[i] = rsqrtf((float)c);
    }
}

// Single-block chunked exclusive scan (1024 threads, shuffle-based).
__global__ void scan_kernel(const int* __restrict__ cnt, int* __restrict__ rowptr, int n) {
    __shared__ int warp_sums[32];
    __shared__ int carry_s;
    int lane = threadIdx.x & 31;
    int warp = threadIdx.x >> 5;
    if (threadIdx.x == 0) { carry_s = 0; rowptr[0] = 0; }
    __syncthreads();
    for (int base = 0; base < n; base += 1024) {
        int i = base + (int)threadIdx.x;
        int v = (i < n) ? cnt[i] : 0;
        int x = v;
        #pragma unroll
        for (int off = 1; off < 32; off <<= 1) {
            int y = __shfl_up_sync(0xffffffffu, x, off);
            if (lane >= off) x += y;
        }
        if (lane == 31) warp_sums[warp] = x;
        __syncthreads();
        if (warp == 0) {
            int s = warp_sums[lane];
            #pragma unroll
            for (int off = 1; off < 32; off <<= 1) {
                int y = __shfl_up_sync(0xffffffffu, s, off);
                if (lane >= off) s += y;
            }
            warp_sums[lane] = s;
        }
        __syncthreads();
        int incl = carry_s + (warp ? warp_sums[warp - 1] : 0) + x;
        if (i < n) rowptr[i + 1] = incl;
        __syncthreads();
        if (threadIdx.x == 1023) carry_s = incl;
        __syncthreads();
    }
}

__global__ void fill_kernel(const int* __restrict__ src, const int* __restrict__ dst,
                            const int* __restrict__ rowptr, int* __restrict__ cursor,
                            int* __restrict__ col, int E) {
    int e = blockIdx.x * blockDim.x + threadIdx.x;
    if (e >= E) return;
    int d = dst[e];
    int pos = atomicAdd(&cursor[d], 1);
    col[rowptr[d] + pos] = src[e];
}

// ---------------------------------------------------------------------------
// Aggregation: out[r] = (relu?)(inv_dst[r] * sum_{c in row r} (inv_src[c]?) * x[c] (+ bias))
// 32 threads per row (float4 lanes), 8 rows per 256-thread block.
// ---------------------------------------------------------------------------

template <bool SRC_SCALE, bool BIAS_RELU>
__global__ void agg_kernel(const float* __restrict__ x, const int* __restrict__ rowptr,
                           const int* __restrict__ col, const float* __restrict__ inv_src,
                           const float* __restrict__ inv_dst, const float* __restrict__ bias,
                           float* __restrict__ out, int n) {
    int r = blockIdx.x * 8 + (int)(threadIdx.x >> 5);
    if (r >= n) return;
    int lane = threadIdx.x & 31;
    int s = rowptr[r], e = rowptr[r + 1];
    float a0 = 0.f, a1 = 0.f, a2 = 0.f, a3 = 0.f;
    int i = s;
    for (; i + 2 <= e; i += 2) {
        int c0 = col[i], c1 = col[i + 1];
        float4 v0 = *reinterpret_cast<const float4*>(x + c0 * 128 + lane * 4);
        float4 v1 = *reinterpret_cast<const float4*>(x + c1 * 128 + lane * 4);
        if (SRC_SCALE) {
            float s0 = inv_src[c0], s1 = inv_src[c1];
            a0 += v0.x * s0 + v1.x * s1;
            a1 += v0.y * s0 + v1.y * s1;
            a2 += v0.z * s0 + v1.z * s1;
            a3 += v0.w * s0 + v1.w * s1;
        } else {
            a0 += v0.x + v1.x;
            a1 += v0.y + v1.y;
            a2 += v0.z + v1.z;
            a3 += v0.w + v1.w;
        }
    }
    if (i < e) {
        int c0 = col[i];
        float4 v0 = *reinterpret_cast<const float4*>(x + c0 * 128 + lane * 4);
        float s0 = SRC_SCALE ? inv_src[c0] : 1.0f;
        a0 += v0.x * s0; a1 += v0.y * s0; a2 += v0.z * s0; a3 += v0.w * s0;
    }
    float sc = inv_dst[r];
    a0 *= sc; a1 *= sc; a2 *= sc; a3 *= sc;
    if (BIAS_RELU) {
        float4 bv = *reinterpret_cast<const float4*>(bias + lane * 4);
        a0 = fmaxf(a0 + bv.x, 0.f);
        a1 = fmaxf(a1 + bv.y, 0.f);
        a2 = fmaxf(a2 + bv.z, 0.f);
        a3 = fmaxf(a3 + bv.w, 0.f);
    }
    float4 o; o.x = a0; o.y = a1; o.z = a2; o.w = a3;
    *reinterpret_cast<float4*>(out + r * 128 + lane * 4) = o;
}

// ---------------------------------------------------------------------------
// GEMM: out[M,128] = (relu?)( (rscale[r]?) * A[M,128] @ W[128,128] (+ bias) )
// BM=128, BN=128, BK=8; 256 threads; 8x8 microtile per thread.
// ---------------------------------------------------------------------------

template <bool ROW_SCALE, bool BIAS_RELU>
__global__ void gemm128(const float* __restrict__ A, const float* __restrict__ W,
                        const float* __restrict__ rscale, const float* __restrict__ bias,
                        float* __restrict__ out, int M) {
    __shared__ float As[8][128];  // [k][m] transposed
    __shared__ float Ws[8][128];  // [k][n]
    int tid = threadIdx.x;  // 0..255
    int block_row = blockIdx.x * 128;
    int tm = (tid >> 4) << 3;  // 0,8,...,120
    int tn = (tid & 15) << 3;  // 0,8,...,120

    float acc[8][8];
    #pragma unroll
    for (int i = 0; i < 8; i++)
        #pragma unroll
        for (int j = 0; j < 8; j++) acc[i][j] = 0.f;

    int ar = tid >> 1;             // 0..127 (row within tile)
    int ap = (tid & 1) * 4;        // 0 or 4 (k offset)
    int wr = tid >> 5;             // 0..7  (k row)
    int wc = (tid & 31) * 4;       // 0..124 (n col)
    int gr_load = block_row + ar;

    float rs = 1.0f;
    if (ROW_SCALE && gr_load < M) rs = rscale[gr_load];

    for (int k0 = 0; k0 < 128; k0 += 8) {
        float4 av = make_float4(0.f, 0.f, 0.f, 0.f);
        if (gr_load < M)
            av = *reinterpret_cast<const float4*>(A + gr_load * 128 + k0 + ap);
        if (ROW_SCALE) { av.x *= rs; av.y *= rs; av.z *= rs; av.w *= rs; }
        As[ap + 0][ar] = av.x;
        As[ap + 1][ar] = av.y;
        As[ap + 2][ar] = av.z;
        As[ap + 3][ar] = av.w;
        *reinterpret_cast<float4*>(&Ws[wr][wc]) =
            *reinterpret_cast<const float4*>(W + (k0 + wr) * 128 + wc);
        __syncthreads();
        #pragma unroll
        for (int kk = 0; kk < 8; kk++) {
            float af[8], wf[8];
            *reinterpret_cast<float4*>(&af[0]) = *reinterpret_cast<float4*>(&As[kk][tm]);
            *reinterpret_cast<float4*>(&af[4]) = *reinterpret_cast<float4*>(&As[kk][tm + 4]);
            *reinterpret_cast<float4*>(&wf[0]) = *reinterpret_cast<float4*>(&Ws[kk][tn]);
            *reinterpret_cast<float4*>(&wf[4]) = *reinterpret_cast<float4*>(&Ws[kk][tn + 4]);
            #pragma unroll
            for (int i = 0; i < 8; i++)
                #pragma unroll
                for (int j = 0; j < 8; j++) acc[i][j] += af[i] * wf[j];
        }
        __syncthreads();
    }

    #pragma unroll
    for (int i = 0; i < 8; i++) {
        int gr = block_row + tm + i;
        if (gr >= M) continue;
        #pragma unroll
        for (int j = 0; j < 8; j += 4) {
            float4 v = make_float4(acc[i][j], acc[i][j + 1], acc[i][j + 2], acc[i][j + 3]);
            if (BIAS_RELU) {
                v.x = fmaxf(v.x + bias[tn + j + 0], 0.f);
                v.y = fmaxf(v.y + bias[tn + j + 1], 0.f);
                v.z = fmaxf(v.z + bias[tn + j + 2], 0.f);
                v.w = fmaxf(v.w + bias[tn + j + 3], 0.f);
            }
            *reinterpret_cast<float4*>(out + gr * 128 + tn + j) = v;
        }
    }
}

// ---------------------------------------------------------------------------
// Launch
// ---------------------------------------------------------------------------

extern "C" void kernel_launch(void* const* d_in, const int* in_sizes, int n_in,
                              void* d_out, int out_size) {
    const float* h_p   = (const float*)d_in[0];
    const float* h_d   = (const float*)d_in[1];
    const int* pd_src  = (const int*)d_in[2];
    const int* pd_dst  = (const int*)d_in[3];
    const int* dp_src  = (const int*)d_in[4];
    const int* dp_dst  = (const int*)d_in[5];
    const float* W1_pd = (const float*)d_in[6];
    const float* b1_pd = (const float*)d_in[7];
    const float* W1_dp = (const float*)d_in[8];
    const float* b1_dp = (const float*)d_in[9];
    const float* W2_pd = (const float*)d_in[10];
    const float* b2_pd = (const float*)d_in[11];
    const float* W2_dp = (const float*)d_in[12];
    const float* b2_dp = (const float*)d_in[13];
    const float* W3_pd = (const float*)d_in[14];
    const float* b3_pd = (const float*)d_in[15];
    const float* W3_dp = (const float*)d_in[16];
    const float* b3_dp = (const float*)d_in[17];

    int E  = in_sizes[2];
    int E2 = in_sizes[4];

    void* base = nullptr;
    cudaGetSymbolAddress(&base, g_mem);
    unsigned char* p = (unsigned char*)base;
    auto bump = [&](size_t bytes) -> void* {
        void* r = (void*)p;
        p += (bytes + 255) & ~(size_t)255;
        return r;
    };

    float* inv_p_out = (float*)bump((size_t)NP * 4);
    float* inv_d_in  = (float*)bump((size_t)ND * 4);
    float* inv_d_out = (float*)bump((size_t)ND * 4);
    float* inv_p_in  = (float*)bump((size_t)NP * 4);
    int* cnt_p_out   = (int*)bump((size_t)NP * 4);
    int* cnt_d_in    = (int*)bump((size_t)ND * 4);
    int* cnt_d_out   = (int*)bump((size_t)ND * 4);
    int* cnt_p_in    = (int*)bump((size_t)NP * 4);
    int* rp_pd       = (int*)bump((size_t)(ND + 1) * 4);
    int* rp_dp       = (int*)bump((size_t)(NP + 1) * 4);
    int* col_pd      = (int*)bump((size_t)EMAX * 4);
    int* col_dp      = (int*)bump((size_t)EMAX * 4);
    float* hd1       = (float*)bump((size_t)ND * 128 * 4);
    float* hd2       = (float*)bump((size_t)ND * 128 * 4);
    float* hp1       = (float*)bump((size_t)NP * 128 * 4);
    float* hp2       = (float*)bump((size_t)NP * 128 * 4);
    float* scr       = (float*)bump((size_t)ND * 128 * 4);

    float* out_p = (float*)d_out;                 // h_p3: [NP,128]
    float* out_d = out_p + (size_t)NP * 128;      // h_d3: [ND,128]

    // --- graph setup (degrees, inv-sqrt, CSR) ---
    cudaMemsetAsync(cnt_p_out, 0, (size_t)NP * 4);
    cudaMemsetAsync(cnt_d_in, 0, (size_t)ND * 4);
    cudaMemsetAsync(cnt_d_out, 0, (size_t)ND * 4);
    cudaMemsetAsync(cnt_p_in, 0, (size_t)NP * 4);

    int gb = (E + 255) / 256;
    int gb2 = (E2 + 255) / 256;
    count_kernel<<<gb, 256>>>(pd_src, cnt_p_out, E);
    count_kernel<<<gb, 256>>>(pd_dst, cnt_d_in, E);
    count_kernel<<<gb2, 256>>>(dp_src, cnt_d_out, E2);
    count_kernel<<<gb2, 256>>>(dp_dst, cnt_p_in, E2);

    inv_kernel<<<(NP + 255) / 256, 256>>>(cnt_p_out, inv_p_out, NP);
    inv_kernel<<<(ND + 255) / 256, 256>>>(cnt_d_in, inv_d_in, ND);
    inv_kernel<<<(ND + 255) / 256, 256>>>(cnt_d_out, inv_d_out, ND);
    inv_kernel<<<(NP + 255) / 256, 256>>>(cnt_p_in, inv_p_in, NP);

    scan_kernel<<<1, 1024>>>(cnt_d_in, rp_pd, ND);
    scan_kernel<<<1, 1024>>>(cnt_p_in, rp_dp, NP);

    cudaMemsetAsync(cnt_d_in, 0, (size_t)ND * 4);
    cudaMemsetAsync(cnt_p_in, 0, (size_t)NP * 4);
    fill_kernel<<<gb, 256>>>(pd_src, pd_dst, rp_pd, cnt_d_in, col_pd, E);
    fill_kernel<<<gb2, 256>>>(dp_src, dp_dst, rp_dp, cnt_p_in, col_dp, E2);

    // --- layers ---
    const int AGG_D_GRID = (ND + 7) / 8;
    const int AGG_P_GRID = (NP + 7) / 8;
    const int GEMM_D_GRID = (ND + 127) / 128;

    auto pd_layer = [&](const float* xin, const float* W, const float* b, float* o) {
        // aggregate p -> d first (GEMM on the smaller 50K side)
        agg_kernel<true, false><<<AGG_D_GRID, 256>>>(xin, rp_pd, col_pd, inv_p_out,
                                                     inv_d_in, nullptr, scr, ND);
        gemm128<false, true><<<GEMM_D_GRID, 256>>>(scr, W, nullptr, b, o, ND);
    };
    auto dp_layer = [&](const float* xin, const float* W, const float* b, float* o) {
        // GEMM first on the 50K d side, then aggregate d -> p
        gemm128<true, false><<<GEMM_D_GRID, 256>>>(xin, W, inv_d_out, nullptr, scr, ND);
        agg_kernel<false, true><<<AGG_P_GRID, 256>>>(scr, rp_dp, col_dp, nullptr,
                                                     inv_p_in, b, o, NP);
    };

    pd_layer(h_p, W1_pd, b1_pd, hd1);
    dp_layer(h_d, W1_dp, b1_dp, hp1);
    pd_layer(hp1, W2_pd, b2_pd, hd2);
    dp_layer(hd1, W2_dp, b2_dp, hp2);
    pd_layer(hp2, W3_pd, b3_pd, out_d);
    dp_layer(hd2, W3_dp, b3_dp, out_p);
}

// round 2
// speedup vs baseline: 1.0054x; 1.0054x over previous
#include <cuda_runtime.h>

#define NP 100000
#define ND 50000
#define EMAX 600000

static const size_t TOTAL_BYTES = 200ull * 1024 * 1024;
__device__ __align__(256) unsigned char g_mem[TOTAL_BYTES];

// ---------------------------------------------------------------------------
// f32x2 helpers (FFMA2 — PTX-only, ptxas never auto-fuses)
// ---------------------------------------------------------------------------

__device__ __forceinline__ unsigned long long pk2(float x, float y) {
    unsigned long long r;
    asm("mov.b64 %0, {%1, %2};" : "=l"(r) : "f"(x), "f"(y));
    return r;
}
__device__ __forceinline__ void fma2(unsigned long long& d, unsigned long long a,
                                     unsigned long long b) {
    asm("fma.rn.f32x2 %0, %1, %2, %0;" : "+l"(d) : "l"(a), "l"(b));
}
__device__ __forceinline__ float2 upk2(unsigned long long v) {
    float2 f;
    asm("mov.b64 {%0, %1}, %2;" : "=f"(f.x), "=f"(f.y) : "l"(v));
    return f;
}

// ---------------------------------------------------------------------------
// Setup kernels: degree count, inv-sqrt, exclusive scan, CSR fill
// ---------------------------------------------------------------------------

__global__ void count_kernel(const int* __restrict__ idx, int* __restrict__ cnt, int E) {
    int e = blockIdx.x * blockDim.x + threadIdx.x;
    if (e < E) atomicAdd(&cnt[idx[e]], 1);
}

__global__ void inv_kernel(const int* __restrict__ cnt, float* __restrict__ inv, int n) {
    int i = blockIdx.x * blockDim.x + threadIdx.x;
    if (i < n) {
        int c = cnt[i];
        if (c < 1) c = 1;
        inv[i] = rsqrtf((float)c);
    }
}

__global__ void scan_kernel(const int* __restrict__ cnt, int* __restrict__ rowptr, int n) {
    __shared__ int warp_sums[32];
    __shared__ int carry_s;
    int lane = threadIdx.x & 31;
    int warp = threadIdx.x >> 5;
    if (threadIdx.x == 0) { carry_s = 0; rowptr[0] = 0; }
    __syncthreads();
    for (int base = 0; base < n; base += 1024) {
        int i = base + (int)threadIdx.x;
        int v = (i < n) ? cnt[i] : 0;
        int x = v;
        #pragma unroll
        for (int off = 1; off < 32; off <<= 1) {
            int y = __shfl_up_sync(0xffffffffu, x, off);
            if (lane >= off) x += y;
        }
        if (lane == 31) warp_sums[warp] = x;
        __syncthreads();
        if (warp == 0) {
            int s = warp_sums[lane];
            #pragma unroll
            for (int off = 1; off < 32; off <<= 1) {
                int y = __shfl_up_sync(0xffffffffu, s, off);
                if (lane >= off) s += y;
            }
            warp_sums[lane] = s;
        }
        __syncthreads();
        int incl = carry_s + (warp ? warp_sums[warp - 1] : 0) + x;
        if (i < n) rowptr[i + 1] = incl;
        __syncthreads();
        if (threadIdx.x == 1023) carry_s = incl;
        __syncthreads();
    }
}

__global__ void fill_kernel(const int* __restrict__ src, const int* __restrict__ dst,
                            const int* __restrict__ rowptr, int* __restrict__ cursor,
                            int* __restrict__ col, int E) {
    int e = blockIdx.x * blockDim.x + threadIdx.x;
    if (e >= E) return;
    int d = dst[e];
    int pos = atomicAdd(&cursor[d], 1);
    col[rowptr[d] + pos] = src[e];
}

// ---------------------------------------------------------------------------
// Aggregation: out[r] = (relu?)(inv_dst[r] * sum_{c in row r} (inv_src[c]?) * x[c] (+ bias))
// 32 threads per row (float4 lanes), 8 rows per 256-thread block. 4-edge unroll for MLP.
// ---------------------------------------------------------------------------

template <bool SRC_SCALE, bool BIAS_RELU>
__global__ void agg_kernel(const float* __restrict__ x, const int* __restrict__ rowptr,
                           const int* __restrict__ col, const float* __restrict__ inv_src,
                           const float* __restrict__ inv_dst, const float* __restrict__ bias,
                           float* __restrict__ out, int n) {
    int r = blockIdx.x * 8 + (int)(threadIdx.x >> 5);
    if (r >= n) return;
    int lane = threadIdx.x & 31;
    int s = rowptr[r], e = rowptr[r + 1];
    float a0 = 0.f, a1 = 0.f, a2 = 0.f, a3 = 0.f;
    int i = s;
    for (; i + 4 <= e; i += 4) {
        int c0 = col[i], c1 = col[i + 1], c2 = col[i + 2], c3 = col[i + 3];
        float4 v0 = *reinterpret_cast<const float4*>(x + c0 * 128 + lane * 4);
        float4 v1 = *reinterpret_cast<const float4*>(x + c1 * 128 + lane * 4);
        float4 v2 = *reinterpret_cast<const float4*>(x + c2 * 128 + lane * 4);
        float4 v3 = *reinterpret_cast<const float4*>(x + c3 * 128 + lane * 4);
        if (SRC_SCALE) {
            float s0 = inv_src[c0], s1 = inv_src[c1], s2 = inv_src[c2], s3 = inv_src[c3];
            a0 += v0.x * s0 + v1.x * s1 + v2.x * s2 + v3.x * s3;
            a1 += v0.y * s0 + v1.y * s1 + v2.y * s2 + v3.y * s3;
            a2 += v0.z * s0 + v1.z * s1 + v2.z * s2 + v3.z * s3;
            a3 += v0.w * s0 + v1.w * s1 + v2.w * s2 + v3.w * s3;
        } else {
            a0 += (v0.x + v1.x) + (v2.x + v3.x);
            a1 += (v0.y + v1.y) + (v2.y + v3.y);
            a2 += (v0.z + v1.z) + (v2.z + v3.z);
            a3 += (v0.w + v1.w) + (v2.w + v3.w);
        }
    }
    for (; i < e; i++) {
        int c0 = col[i];
        float4 v0 = *reinterpret_cast<const float4*>(x + c0 * 128 + lane * 4);
        float s0 = SRC_SCALE ? inv_src[c0] : 1.0f;
        a0 += v0.x * s0; a1 += v0.y * s0; a2 += v0.z * s0; a3 += v0.w * s0;
    }
    float sc = inv_dst[r];
    a0 *= sc; a1 *= sc; a2 *= sc; a3 *= sc;
    if (BIAS_RELU) {
        float4 bv = *reinterpret_cast<const float4*>(bias + lane * 4);
        a0 = fmaxf(a0 + bv.x, 0.f);
        a1 = fmaxf(a1 + bv.y, 0.f);
        a2 = fmaxf(a2 + bv.z, 0.f);
        a3 = fmaxf(a3 + bv.w, 0.f);
    }
    float4 o; o.x = a0; o.y = a1; o.z = a2; o.w = a3;
    *reinterpret_cast<float4*>(out + r * 128 + lane * 4) = o;
}

// ---------------------------------------------------------------------------
// GEMM: out[M,128] = (relu?)( (rscale[r]?) * A[M,128] @ W[128,128] (+ bias) )
// BM=BN=128, BK=8; 256 threads; 8x8 microtile per thread; FFMA2 accumulation.
// ---------------------------------------------------------------------------

template <bool ROW_SCALE, bool BIAS_RELU>
__global__ void gemm128(const float* __restrict__ A, const float* __restrict__ W,
                        const float* __restrict__ rscale, const float* __restrict__ bias,
                        float* __restrict__ out, int M) {
    __shared__ float As[8][128];  // [k][m] transposed
    __shared__ float Ws[8][128];  // [k][n]
    int tid = threadIdx.x;
    int block_row = blockIdx.x * 128;
    int tm = (tid >> 4) << 3;
    int tn = (tid & 15) << 3;

    unsigned long long acc[8][4];  // [m][n-pair]
    #pragma unroll
    for (int i = 0; i < 8; i++)
        #pragma unroll
        for (int j = 0; j < 4; j++) acc[i][j] = 0ull;

    int ar = tid >> 1;
    int ap = (tid & 1) * 4;
    int wr = tid >> 5;
    int wc = (tid & 31) * 4;
    int gr_load = block_row + ar;

    float rs = 1.0f;
    if (ROW_SCALE && gr_load < M) rs = rscale[gr_load];

    for (int k0 = 0; k0 < 128; k0 += 8) {
        float4 av = make_float4(0.f, 0.f, 0.f, 0.f);
        if (gr_load < M)
            av = *reinterpret_cast<const float4*>(A + gr_load * 128 + k0 + ap);
        if (ROW_SCALE) { av.x *= rs; av.y *= rs; av.z *= rs; av.w *= rs; }
        As[ap + 0][ar] = av.x;
        As[ap + 1][ar] = av.y;
        As[ap + 2][ar] = av.z;
        As[ap + 3][ar] = av.w;
        *reinterpret_cast<float4*>(&Ws[wr][wc]) =
            *reinterpret_cast<const float4*>(W + (k0 + wr) * 128 + wc);
        __syncthreads();
        #pragma unroll
        for (int kk = 0; kk < 8; kk++) {
            float4 a0 = *reinterpret_cast<float4*>(&As[kk][tm]);
            float4 a1 = *reinterpret_cast<float4*>(&As[kk][tm + 4]);
            float4 w0 = *reinterpret_cast<float4*>(&Ws[kk][tn]);
            float4 w1 = *reinterpret_cast<float4*>(&Ws[kk][tn + 4]);
            unsigned long long wp[4];
            wp[0] = pk2(w0.x, w0.y);
            wp[1] = pk2(w0.z, w0.w);
            wp[2] = pk2(w1.x, w1.y);
            wp[3] = pk2(w1.z, w1.w);
            float af[8] = {a0.x, a0.y, a0.z, a0.w, a1.x, a1.y, a1.z, a1.w};
            #pragma unroll
            for (int i = 0; i < 8; i++) {
                unsigned long long ai = pk2(af[i], af[i]);
                #pragma unroll
                for (int j = 0; j < 4; j++) fma2(acc[i][j], ai, wp[j]);
            }
        }
        __syncthreads();
    }

    #pragma unroll
    for (int i = 0; i < 8; i++) {
        int gr = block_row + tm + i;
        if (gr >= M) continue;
        #pragma unroll
        for (int j = 0; j < 2; j++) {
            float2 p0 = upk2(acc[i][j * 2 + 0]);
            float2 p1 = upk2(acc[i][j * 2 + 1]);
            float4 v = make_float4(p0.x, p0.y, p1.x, p1.y);
            if (BIAS_RELU) {
                v.x = fmaxf(v.x + bias[tn + j * 4 + 0], 0.f);
                v.y = fmaxf(v.y + bias[tn + j * 4 + 1], 0.f);
                v.z = fmaxf(v.z + bias[tn + j * 4 + 2], 0.f);
                v.w = fmaxf(v.w + bias[tn + j * 4 + 3], 0.f);
            }
            *reinterpret_cast<float4*>(out + gr * 128 + tn + j * 4) = v;
        }
    }
}

// ---------------------------------------------------------------------------
// Launch
// ---------------------------------------------------------------------------

extern "C" void kernel_launch(void* const* d_in, const int* in_sizes, int n_in,
                              void* d_out, int out_size) {
    const float* h_p   = (const float*)d_in[0];
    const float* h_d   = (const float*)d_in[1];
    const int* pd_src  = (const int*)d_in[2];
    const int* pd_dst  = (const int*)d_in[3];
    const int* dp_src  = (const int*)d_in[4];
    const int* dp_dst  = (const int*)d_in[5];
    const float* W1_pd = (const float*)d_in[6];
    const float* b1_pd = (const float*)d_in[7];
    const float* W1_dp = (const float*)d_in[8];
    const float* b1_dp = (const float*)d_in[9];
    const float* W2_pd = (const float*)d_in[10];
    const float* b2_pd = (const float*)d_in[11];
    const float* W2_dp = (const float*)d_in[12];
    const float* b2_dp = (const float*)d_in[13];
    const float* W3_pd = (const float*)d_in[14];
    const float* b3_pd = (const float*)d_in[15];
    const float* W3_dp = (const float*)d_in[16];
    const float* b3_dp = (const float*)d_in[17];

    int E  = in_sizes[2];
    int E2 = in_sizes[4];

    void* base = nullptr;
    cudaGetSymbolAddress(&base, g_mem);
    unsigned char* p = (unsigned char*)base;
    auto bump = [&](size_t bytes) -> void* {
        void* r = (void*)p;
        p += (bytes + 255) & ~(size_t)255;
        return r;
    };

    float* inv_p_out = (float*)bump((size_t)NP * 4);
    float* inv_d_in  = (float*)bump((size_t)ND * 4);
    float* inv_d_out = (float*)bump((size_t)ND * 4);
    float* inv_p_in  = (float*)bump((size_t)NP * 4);
    int* cnt_p_out   = (int*)bump((size_t)NP * 4);
    int* cnt_d_in    = (int*)bump((size_t)ND * 4);
    int* cnt_d_out   = (int*)bump((size_t)ND * 4);
    int* cnt_p_in    = (int*)bump((size_t)NP * 4);
    int* rp_pd       = (int*)bump((size_t)(ND + 1) * 4);
    int* rp_dp       = (int*)bump((size_t)(NP + 1) * 4);
    int* col_pd      = (int*)bump((size_t)EMAX * 4);
    int* col_dp      = (int*)bump((size_t)EMAX * 4);
    float* hd1       = (float*)bump((size_t)ND * 128 * 4);
    float* hd2       = (float*)bump((size_t)ND * 128 * 4);
    float* hp1       = (float*)bump((size_t)NP * 128 * 4);
    float* hp2       = (float*)bump((size_t)NP * 128 * 4);
    float* scr       = (float*)bump((size_t)ND * 128 * 4);

    float* out_p = (float*)d_out;
    float* out_d = out_p + (size_t)NP * 128;

    cudaMemsetAsync(cnt_p_out, 0, (size_t)NP * 4);
    cudaMemsetAsync(cnt_d_in, 0, (size_t)ND * 4);
    cudaMemsetAsync(cnt_d_out, 0, (size_t)ND * 4);
    cudaMemsetAsync(cnt_p_in, 0, (size_t)NP * 4);

    int gb = (E + 255) / 256;
    int gb2 = (E2 + 255) / 256;
    count_kernel<<<gb, 256>>>(pd_src, cnt_p_out, E);
    count_kernel<<<gb, 256>>>(pd_dst, cnt_d_in, E);
    count_kernel<<<gb2, 256>>>(dp_src, cnt_d_out, E2);
    count_kernel<<<gb2, 256>>>(dp_dst, cnt_p_in, E2);

    inv_kernel<<<(NP + 255) / 256, 256>>>(cnt_p_out, inv_p_out, NP);
    inv_kernel<<<(ND + 255) / 256, 256>>>(cnt_d_in, inv_d_in, ND);
    inv_kernel<<<(ND + 255) / 256, 256>>>(cnt_d_out, inv_d_out, ND);
    inv_kernel<<<(NP + 255) / 256, 256>>>(cnt_p_in, inv_p_in, NP);

    scan_kernel<<<1, 1024>>>(cnt_d_in, rp_pd, ND);
    scan_kernel<<<1, 1024>>>(cnt_p_in, rp_dp, NP);

    cudaMemsetAsync(cnt_d_in, 0, (size_t)ND * 4);
    cudaMemsetAsync(cnt_p_in, 0, (size_t)NP * 4);
    fill_kernel<<<gb, 256>>>(pd_src, pd_dst, rp_pd, cnt_d_in, col_pd, E);
    fill_kernel<<<gb2, 256>>>(dp_src, dp_dst, rp_dp, cnt_p_in, col_dp, E2);

    const int AGG_D_GRID = (ND + 7) / 8;
    const int AGG_P_GRID = (NP + 7) / 8;
    const int GEMM_D_GRID = (ND + 127) / 128;

    auto pd_layer = [&](const float* xin, const float* W, const float* b, float* o) {
        agg_kernel<true, false><<<AGG_D_GRID, 256>>>(xin, rp_pd, col_pd, inv_p_out,
                                                     inv_d_in, nullptr, scr, ND);
        gemm128<false, true><<<GEMM_D_GRID, 256>>>(scr, W, nullptr, b, o, ND);
    };
    auto dp_layer = [&](const float* xin, const float* W, const float* b, float* o) {
        gemm128<true, false><<<GEMM_D_GRID, 256>>>(xin, W, inv_d_out, nullptr, scr, ND);
        agg_kernel<false, true><<<AGG_P_GRID, 256>>>(scr, rp_dp, col_dp, nullptr,
                                                     inv_p_in, b, o, NP);
    };

    pd_layer(h_p, W1_pd, b1_pd, hd1);
    dp_layer(h_d, W1_dp, b1_dp, hp1);
    pd_layer(hp1, W2_pd, b2_pd, hd2);
    dp_layer(hd1, W2_dp, b2_dp, hp2);
    pd_layer(hp2, W3_pd, b3_pd, out_d);
    dp_layer(hd2, W3_dp, b3_dp, out_p);
}